// round 14
// baseline (speedup 1.0000x reference)
#include <cuda_runtime.h>
#include <cstdint>

#define Bsz   65536
#define Dsz   1024
#define Hsz   8

#define ROWS_PER_CTA 128
#define NT           256
#define KC           64
#define NSTAGES      16
#define RS           68          // smem x-row stride (floats): 272B, conflict-free
#define SGS          34          // gate-exchange row stride (floats), EVEN -> float2-aligned

// smem layout (bytes)
#define WH_OFF     64
#define BZ_OFF     1088
#define ZW_OFF     1216
#define WD1_OFF    1344
#define BD1_OFF    1504
#define WD2_OFF    1536
#define BD2_OFF    1664
#define WD3_OFF    1696
#define BD3_OFF    1720
#define M1_OFF     1728
#define M2_OFF     1760
#define XS_OFF     4096
#define XS_SZ      (ROWS_PER_CTA * RS * 4)            // 34816
#define WS_OFF     (XS_OFF + 2 * XS_SZ)               // 73728
#define WS_SZ      8192                               // 4 kt * 4 nt * 32 lanes * 16B
#define SMEM_TOTAL (WS_OFF + 2 * WS_SZ)               // 90112
#define SG_OFF     XS_OFF

// pre-packed B fragments: [stage 16][kt 4][nt 4][lane 32] uint4 = (bh0,bh1,bl0,bl1)
__device__ __align__(16) uint4 g_Bp[NSTAGES * 4 * 4 * 32];

__device__ __forceinline__ uint32_t cvtbf2(float hi, float lo) {
    uint32_t r;
    asm("cvt.rn.bf16x2.f32 %0, %1, %2;" : "=r"(r) : "f"(hi), "f"(lo));
    return r;
}
__device__ __forceinline__ float bf_lo(uint32_t u) { return __uint_as_float(u << 16); }
__device__ __forceinline__ float bf_hi(uint32_t u) { return __uint_as_float(u & 0xffff0000u); }

__device__ __forceinline__ void cp16(uint32_t dst, const void* src) {
    asm volatile("cp.async.cg.shared.global [%0], [%1], 16;" :: "r"(dst), "l"(src) : "memory");
}
#define CP_COMMIT() asm volatile("cp.async.commit_group;" ::: "memory")
#define CP_WAIT1()  asm volatile("cp.async.wait_group 1;" ::: "memory")
#define CP_WAIT0()  asm volatile("cp.async.wait_group 0;" ::: "memory")

__device__ __forceinline__ float hsig(float x) {
    return __saturatef(fmaf(x, 0.16666667f, 0.5f));
}
__device__ __forceinline__ void mma16816(float* c, uint32_t a0, uint32_t a1, uint32_t a2, uint32_t a3,
                                         uint32_t b0, uint32_t b1) {
    asm volatile(
        "mma.sync.aligned.m16n8k16.row.col.f32.bf16.bf16.f32 "
        "{%0,%1,%2,%3},{%4,%5,%6,%7},{%8,%9},{%0,%1,%2,%3};"
        : "+f"(c[0]), "+f"(c[1]), "+f"(c[2]), "+f"(c[3])
        : "r"(a0), "r"(a1), "r"(a2), "r"(a3), "r"(b0), "r"(b1));
}

// ---------------- prep: fold m_x into W, split bf16 hi/lo, pack mma B fragments ----------------
__global__ void prep_B(const float* __restrict__ Wxi, const float* __restrict__ Wxf,
                       const float* __restrict__ Wxc, const float* __restrict__ Wxo,
                       const float* __restrict__ mx) {
    int i = blockIdx.x * blockDim.x + threadIdx.x;
    if (i >= 64 * 4 * 32) return;
    int lane = i & 31;
    int nt   = (i >> 5) & 3;
    int ktg  = i >> 7;            // global k-tile 0..63
    int g    = lane >> 2;
    int t4   = lane & 3;
    int n    = nt * 8 + g;        // output col 0..31
    int gate = n >> 3, nn = n & 7;
    const float* W = (gate == 0) ? Wxi : (gate == 1) ? Wxf : (gate == 2) ? Wxc : Wxo;
    int kb = ktg * 16 + t4 * 2;
    float w00 = mx[gate * Dsz + kb]     * W[kb * Hsz + nn];
    float w01 = mx[gate * Dsz + kb + 1] * W[(kb + 1) * Hsz + nn];
    float w10 = mx[gate * Dsz + kb + 8] * W[(kb + 8) * Hsz + nn];
    float w11 = mx[gate * Dsz + kb + 9] * W[(kb + 9) * Hsz + nn];
    uint4 v;
    v.x = cvtbf2(w01, w00);                                   // bh0 (k lo pair)
    v.y = cvtbf2(w11, w10);                                   // bh1 (k hi pair)
    v.z = cvtbf2(w01 - bf_hi(v.x), w00 - bf_lo(v.x));         // bl0
    v.w = cvtbf2(w11 - bf_hi(v.y), w10 - bf_lo(v.y));         // bl1
    int stage = ktg >> 2, kt = ktg & 3;
    g_Bp[((stage * 4 + kt) * 4 + nt) * 32 + lane] = v;
}

struct KParams {
    const float *x, *hp, *cp, *zp;
    const float *Whi, *Whf, *Whc, *Who;
    const float *Wzi, *Wzf, *Wzc, *Wzo;
    const float *bi, *bf, *bc, *bo;
    const float *Wd1, *bd1, *Wd2, *bd2, *Wd3, *bd3;
    const float *mz, *m1, *m2;
    float *out;
};

// per-stage async copy: x slice (128 rows x 256B) + W frags (8KB), via LDGSTS
__device__ __forceinline__ void issue_stage(int s, uint32_t smem_u32, const float* x,
                                            int cta_row0, int tid) {
    int buf = s & 1;
    int row  = tid >> 1;
    int half = tid & 1;
    uint32_t dstx = smem_u32 + XS_OFF + (uint32_t)buf * XS_SZ + (uint32_t)row * (RS * 4) + (uint32_t)half * 128;
    const char* srcx = (const char*)(x + (size_t)(cta_row0 + row) * Dsz + (size_t)s * KC) + half * 128;
#pragma unroll
    for (int i = 0; i < 8; i++) cp16(dstx + i * 16, srcx + i * 16);
    uint32_t dstw = smem_u32 + WS_OFF + (uint32_t)buf * WS_SZ + (uint32_t)tid * 16;
    const char* srcw = (const char*)g_Bp + (size_t)s * WS_SZ + (size_t)tid * 16;
    cp16(dstw, srcw);
    cp16(dstw + 4096, srcw + 4096);
    CP_COMMIT();
}

__global__ void __launch_bounds__(NT, 2)
lstm_kernel(KParams p) {
    extern __shared__ char smem[];
    const int tid = threadIdx.x;
    const int w   = tid >> 5;        // warp = m-tile (16 rows)
    const int lane = tid & 31;
    const int g   = lane >> 2;
    const int t4  = lane & 3;
    const int lr0 = w * 16 + g;      // local row for frag rows g
    const int lr1 = lr0 + 8;
    const int cta_row0 = blockIdx.x * ROWS_PER_CTA;

    uint32_t smem_u32 = (uint32_t)__cvta_generic_to_shared(smem);

    {
        float* sWh = (float*)(smem + WH_OFF);
        if (tid < 256) {
            int j = tid >> 5, n = tid & 31, gg = n >> 3, nn = n & 7;
            const float* Wh = (gg == 0) ? p.Whi : (gg == 1) ? p.Whf : (gg == 2) ? p.Whc : p.Who;
            sWh[j * 32 + n] = Wh[j * Hsz + nn];
        }
        if (tid < 32) {
            int gg = tid >> 3, nn = tid & 7;
            const float* b  = (gg == 0) ? p.bi  : (gg == 1) ? p.bf  : (gg == 2) ? p.bc  : p.bo;
            const float* Wz = (gg == 0) ? p.Wzi : (gg == 1) ? p.Wzf : (gg == 2) ? p.Wzc : p.Wzo;
            ((float*)(smem + BZ_OFF))[tid] = b[nn];
            ((float*)(smem + ZW_OFF))[tid] = p.mz[gg] * Wz[nn];
        }
        if (tid >= 32 && tid < 72)  ((float*)(smem + WD1_OFF))[tid - 32] = p.Wd1[tid - 32];
        if (tid >= 72 && tid < 97)  ((float*)(smem + WD2_OFF))[tid - 72] = p.Wd2[tid - 72];
        if (tid >= 97 && tid < 102) {
            int q = tid - 97;
            ((float*)(smem + WD3_OFF))[q] = p.Wd3[q];
            ((float*)(smem + BD1_OFF))[q] = p.bd1[q];
            ((float*)(smem + BD2_OFF))[q] = p.bd2[q];
            ((float*)(smem + M1_OFF))[q]  = p.m1[q];
            ((float*)(smem + M2_OFF))[q]  = p.m2[q];
        }
        if (tid == 102) ((float*)(smem + BD3_OFF))[0] = p.bd3[0];
    }

    issue_stage(0, smem_u32, p.x, cta_row0, tid);
    issue_stage(1, smem_u32, p.x, cta_row0, tid);

    float acc[4][4];
#pragma unroll
    for (int nt = 0; nt < 4; nt++)
#pragma unroll
        for (int q = 0; q < 4; q++) acc[nt][q] = 0.0f;

    for (int s = 0; s < NSTAGES; s++) {
        int buf = s & 1;
        if (s < NSTAGES - 2) CP_WAIT1(); else CP_WAIT0();
        __syncthreads();

        const float* xsb = (const float*)(smem + XS_OFF + buf * XS_SZ);
        const uint4* ws  = (const uint4*)(smem + WS_OFF + buf * WS_SZ);
        const float* xg  = xsb + lr0 * RS + 2 * t4;
        const float* xg8 = xsb + lr1 * RS + 2 * t4;

#pragma unroll
        for (int kt = 0; kt < 4; kt++) {
            float2 xa = *(const float2*)(xg  + kt * 16);
            float2 xb = *(const float2*)(xg  + kt * 16 + 8);
            float2 xc = *(const float2*)(xg8 + kt * 16);
            float2 xd = *(const float2*)(xg8 + kt * 16 + 8);
            uint32_t ah0 = cvtbf2(xa.y, xa.x);
            uint32_t ah1 = cvtbf2(xc.y, xc.x);
            uint32_t ah2 = cvtbf2(xb.y, xb.x);
            uint32_t ah3 = cvtbf2(xd.y, xd.x);
            uint32_t al0 = cvtbf2(xa.y - bf_hi(ah0), xa.x - bf_lo(ah0));
            uint32_t al1 = cvtbf2(xc.y - bf_hi(ah1), xc.x - bf_lo(ah1));
            uint32_t al2 = cvtbf2(xb.y - bf_hi(ah2), xb.x - bf_lo(ah2));
            uint32_t al3 = cvtbf2(xd.y - bf_hi(ah3), xd.x - bf_lo(ah3));
#pragma unroll
            for (int nt = 0; nt < 4; nt++) {
                uint4 bv = ws[(kt * 4 + nt) * 32 + lane];
                mma16816(acc[nt], ah0, ah1, ah2, ah3, bv.x, bv.y);   // xh @ Wh
                mma16816(acc[nt], al0, al1, al2, al3, bv.x, bv.y);   // xl @ Wh
                mma16816(acc[nt], ah0, ah1, ah2, ah3, bv.z, bv.w);   // xh @ Wl
            }
        }
        __syncthreads();
        if (s + 2 < NSTAGES) issue_stage(s + 2, smem_u32, p.x, cta_row0, tid);
    }

    // exchange pre-activations: sg[row][n]
    float* sg = (float*)(smem + SG_OFF);
#pragma unroll
    for (int nt = 0; nt < 4; nt++) {
        *(float2*)&sg[lr0 * SGS + nt * 8 + 2 * t4] = make_float2(acc[nt][0], acc[nt][1]);
        *(float2*)&sg[lr1 * SGS + nt * 8 + 2 * t4] = make_float2(acc[nt][2], acc[nt][3]);
    }
    __syncthreads();

    if (tid < ROWS_PER_CTA) {
        const int rg = cta_row0 + tid;
        const float* sWh = (const float*)(smem + WH_OFF);
        const float* sbz = (const float*)(smem + BZ_OFF);
        const float* szw = (const float*)(smem + ZW_OFF);
        const float* sd1 = (const float*)(smem + WD1_OFF);
        const float* sb1 = (const float*)(smem + BD1_OFF);
        const float* sd2 = (const float*)(smem + WD2_OFF);
        const float* sb2 = (const float*)(smem + BD2_OFF);
        const float* sd3 = (const float*)(smem + WD3_OFF);
        const float  b3  = ((const float*)(smem + BD3_OFF))[0];
        const float* sm1 = (const float*)(smem + M1_OFF);
        const float* sm2 = (const float*)(smem + M2_OFF);

        float pre[32];
#pragma unroll
        for (int n = 0; n < 32; n++) pre[n] = sg[tid * SGS + n];

        float zv = p.zp[rg];
        float hv[8];
#pragma unroll
        for (int j = 0; j < 8; j++) hv[j] = p.hp[(size_t)rg * Hsz + j];

#pragma unroll
        for (int n = 0; n < 32; n++) pre[n] = fmaf(zv, szw[n], pre[n] + sbz[n]);
#pragma unroll
        for (int j = 0; j < 8; j++) {
#pragma unroll
            for (int n = 0; n < 32; n++) pre[n] = fmaf(hv[j], sWh[j * 32 + n], pre[n]);
        }

        float htv[8];
        float* out = p.out;
#pragma unroll
        for (int nn = 0; nn < 8; nn++) {
            float cprev = p.cp[(size_t)rg * Hsz + nn];
            float It = hsig(pre[nn]);
            float Ft = hsig(pre[8 + nn]);
            float Cc = tanhf(pre[16 + nn]);
            float Ot = hsig(pre[24 + nn]);
            float cn = fmaf(Ft, cprev, It * Cc);
            htv[nn] = Ot * tanhf(cn);
            out[(size_t)Bsz * 9 + (size_t)rg * Hsz + nn] = cn;       // ct
            out[(size_t)Bsz     + (size_t)rg * Hsz + nn] = htv[nn];  // ht
        }

        float t1[5];
#pragma unroll
        for (int q = 0; q < 5; q++) {
            float a = sb1[q];
#pragma unroll
            for (int nn = 0; nn < 8; nn++) a = fmaf(htv[nn], sd1[nn * 5 + q], a);
            t1[q] = fmaxf(a, 0.0f) * sm1[q];
        }
        float t2[5];
#pragma unroll
        for (int q = 0; q < 5; q++) {
            float a = sb2[q];
#pragma unroll
            for (int u = 0; u < 5; u++) a = fmaf(t1[u], sd2[u * 5 + q], a);
            t2[q] = fmaxf(a, 0.0f) * sm2[q];
        }
        float a3 = b3;
#pragma unroll
        for (int u = 0; u < 5; u++) a3 = fmaf(t2[u], sd3[u], a3);
        out[rg] = zv + fmaxf(a3, 0.0f);                              // zt
    }
}

extern "C" void kernel_launch(void* const* d_in, const int* in_sizes, int n_in,
                              void* d_out, int out_size) {
    KParams p;
    p.x   = (const float*)d_in[0];
    p.hp  = (const float*)d_in[1];
    p.cp  = (const float*)d_in[2];
    p.zp  = (const float*)d_in[3];
    const float* Wxi = (const float*)d_in[4];
    const float* Wxf = (const float*)d_in[5];
    const float* Wxc = (const float*)d_in[6];
    const float* Wxo = (const float*)d_in[7];
    p.Whi = (const float*)d_in[8];
    p.Whf = (const float*)d_in[9];
    p.Whc = (const float*)d_in[10];
    p.Who = (const float*)d_in[11];
    p.Wzi = (const float*)d_in[12];
    p.Wzf = (const float*)d_in[13];
    p.Wzc = (const float*)d_in[14];
    p.Wzo = (const float*)d_in[15];
    p.bi  = (const float*)d_in[16];
    p.bf  = (const float*)d_in[17];
    p.bc  = (const float*)d_in[18];
    p.bo  = (const float*)d_in[19];
    p.Wd1 = (const float*)d_in[20];
    p.bd1 = (const float*)d_in[21];
    p.Wd2 = (const float*)d_in[22];
    p.bd2 = (const float*)d_in[23];
    p.Wd3 = (const float*)d_in[24];
    p.bd3 = (const float*)d_in[25];
    const float* mx = (const float*)d_in[26];
    p.mz  = (const float*)d_in[27];
    p.m1  = (const float*)d_in[28];
    p.m2  = (const float*)d_in[29];
    p.out = (float*)d_out;

    cudaFuncSetAttribute(lstm_kernel, cudaFuncAttributeMaxDynamicSharedMemorySize, SMEM_TOTAL);

    prep_B<<<(64 * 4 * 32 + 255) / 256, 256>>>(Wxi, Wxf, Wxc, Wxo, mx);
    lstm_kernel<<<Bsz / ROWS_PER_CTA, NT, SMEM_TOTAL>>>(p);
}

// round 15
// speedup vs baseline: 1.8606x; 1.8606x over previous
#include <cuda_runtime.h>
#include <cuda.h>
#include <cstdint>

#define Bsz   65536
#define Dsz   1024
#define Hsz   8

#define ROWS_PER_CTA 128
#define NT           256
#define KC           64
#define NSTAGES      16
#define SGS          34          // gate-exchange row stride (floats), EVEN -> float2-aligned

// smem layout (bytes)
#define MBAR_OFF   0             // 2 mbars
#define WH_OFF     64
#define BZ_OFF     1088
#define ZW_OFF     1216
#define WD1_OFF    1344
#define BD1_OFF    1504
#define WD2_OFF    1536
#define BD2_OFF    1664
#define WD3_OFF    1696
#define BD3_OFF    1720
#define M1_OFF     1728
#define M2_OFF     1760
#define XS_OFF     4096
#define XS_SZ      32768                              // 2 subtiles x (128 rows x 128B), SW128
#define WS_OFF     (XS_OFF + 2 * XS_SZ)               // 69632
#define WS_SZ      8192                               // 4 kt * 4 nt * 32 lanes * 16B
#define SMEM_TOTAL (WS_OFF + 2 * WS_SZ)               // 86016
#define SG_OFF     XS_OFF
#define STAGE_BYTES (XS_SZ + WS_SZ)                   // 40960

// pre-packed B fragments: [stage 16][kt 4][nt 4][lane 32] uint4 = (bh0,bh1,bl0,bl1)
__device__ __align__(16) uint4 g_Bp[NSTAGES * 4 * 4 * 32];

__device__ __forceinline__ uint32_t cvtbf2(float hi, float lo) {
    uint32_t r;
    asm("cvt.rn.bf16x2.f32 %0, %1, %2;" : "=r"(r) : "f"(hi), "f"(lo));
    return r;
}
__device__ __forceinline__ float bf_lo(uint32_t u) { return __uint_as_float(u << 16); }
__device__ __forceinline__ float bf_hi(uint32_t u) { return __uint_as_float(u & 0xffff0000u); }

__device__ __forceinline__ void mbar_init(uint32_t a, uint32_t cnt) {
    asm volatile("mbarrier.init.shared.b64 [%0], %1;" :: "r"(a), "r"(cnt) : "memory");
}
__device__ __forceinline__ void mbar_expect_tx(uint32_t a, uint32_t bytes) {
    asm volatile("mbarrier.arrive.expect_tx.shared.b64 _, [%0], %1;" :: "r"(a), "r"(bytes) : "memory");
}
__device__ __forceinline__ void mbar_wait(uint32_t a, uint32_t parity) {
    asm volatile(
        "{\n\t.reg .pred P;\n"
        "LW_%=:\n\t"
        "mbarrier.try_wait.parity.acquire.cta.shared::cta.b64 P, [%0], %1, 0x989680;\n\t"
        "@P bra LD_%=;\n\t"
        "bra LW_%=;\n"
        "LD_%=:\n\t}"
        :: "r"(a), "r"(parity) : "memory");
}
__device__ __forceinline__ void bulk_g2s(uint32_t dst, const void* src, uint32_t bytes, uint32_t mbar) {
    asm volatile(
        "cp.async.bulk.shared::cluster.global.mbarrier::complete_tx::bytes [%0], [%1], %2, [%3];"
        :: "r"(dst), "l"(src), "r"(bytes), "r"(mbar) : "memory");
}
__device__ __forceinline__ void tma2d(uint32_t dst, const CUtensorMap* tm, int c0, int c1, uint32_t mbar) {
    asm volatile(
        "cp.async.bulk.tensor.2d.shared::cluster.global.tile.mbarrier::complete_tx::bytes "
        "[%0], [%1, {%2, %3}], [%4];"
        :: "r"(dst), "l"(tm), "r"(c0), "r"(c1), "r"(mbar) : "memory");
}
__device__ __forceinline__ float hsig(float x) {
    return __saturatef(fmaf(x, 0.16666667f, 0.5f));
}
__device__ __forceinline__ void mma16816(float* c, uint32_t a0, uint32_t a1, uint32_t a2, uint32_t a3,
                                         uint32_t b0, uint32_t b1) {
    asm volatile(
        "mma.sync.aligned.m16n8k16.row.col.f32.bf16.bf16.f32 "
        "{%0,%1,%2,%3},{%4,%5,%6,%7},{%8,%9},{%0,%1,%2,%3};"
        : "+f"(c[0]), "+f"(c[1]), "+f"(c[2]), "+f"(c[3])
        : "r"(a0), "r"(a1), "r"(a2), "r"(a3), "r"(b0), "r"(b1));
}

// ---------------- prep: fold m_x into W, split bf16 hi/lo, pack mma B fragments ----------------
__global__ void prep_B(const float* __restrict__ Wxi, const float* __restrict__ Wxf,
                       const float* __restrict__ Wxc, const float* __restrict__ Wxo,
                       const float* __restrict__ mx) {
    int i = blockIdx.x * blockDim.x + threadIdx.x;
    if (i >= 64 * 4 * 32) return;
    int lane = i & 31;
    int nt   = (i >> 5) & 3;
    int ktg  = i >> 7;            // global k-tile 0..63
    int g    = lane >> 2;
    int t4   = lane & 3;
    int n    = nt * 8 + g;        // output col 0..31
    int gate = n >> 3, nn = n & 7;
    const float* W = (gate == 0) ? Wxi : (gate == 1) ? Wxf : (gate == 2) ? Wxc : Wxo;
    int kb = ktg * 16 + t4 * 2;
    float w00 = mx[gate * Dsz + kb]     * W[kb * Hsz + nn];
    float w01 = mx[gate * Dsz + kb + 1] * W[(kb + 1) * Hsz + nn];
    float w10 = mx[gate * Dsz + kb + 8] * W[(kb + 8) * Hsz + nn];
    float w11 = mx[gate * Dsz + kb + 9] * W[(kb + 9) * Hsz + nn];
    uint4 v;
    v.x = cvtbf2(w01, w00);
    v.y = cvtbf2(w11, w10);
    v.z = cvtbf2(w01 - bf_hi(v.x), w00 - bf_lo(v.x));
    v.w = cvtbf2(w11 - bf_hi(v.y), w10 - bf_lo(v.y));
    int stage = ktg >> 2, kt = ktg & 3;
    g_Bp[((stage * 4 + kt) * 4 + nt) * 32 + lane] = v;
}

struct KParams {
    const float *x, *hp, *cp, *zp;
    const float *Whi, *Whf, *Whc, *Who;
    const float *Wzi, *Wzf, *Wzc, *Wzo;
    const float *bi, *bf, *bc, *bo;
    const float *Wd1, *bd1, *Wd2, *bd2, *Wd3, *bd3;
    const float *mz, *m1, *m2;
    float *out;
};

__global__ void __launch_bounds__(NT, 2)
lstm_kernel(KParams p, const __grid_constant__ CUtensorMap tmx) {
    extern __shared__ char smem[];
    const int tid = threadIdx.x;
    const int w   = tid >> 5;        // warp = m-tile (16 rows)
    const int lane = tid & 31;
    const int g   = lane >> 2;
    const int t4  = lane & 3;
    const int lr0 = w * 16 + g;
    const int lr1 = lr0 + 8;
    const int cta_row0 = blockIdx.x * ROWS_PER_CTA;
    const CUtensorMap* tmp_x = &tmx;

    uint32_t smem_u32 = (uint32_t)__cvta_generic_to_shared(smem);

    if (tid == 0) {
        mbar_init(smem_u32 + MBAR_OFF + 0, 1);
        mbar_init(smem_u32 + MBAR_OFF + 8, 1);
    }
    {
        float* sWh = (float*)(smem + WH_OFF);
        if (tid < 256) {
            int j = tid >> 5, n = tid & 31, gg = n >> 3, nn = n & 7;
            const float* Wh = (gg == 0) ? p.Whi : (gg == 1) ? p.Whf : (gg == 2) ? p.Whc : p.Who;
            sWh[j * 32 + n] = Wh[j * Hsz + nn];
        }
        if (tid < 32) {
            int gg = tid >> 3, nn = tid & 7;
            const float* b  = (gg == 0) ? p.bi  : (gg == 1) ? p.bf  : (gg == 2) ? p.bc  : p.bo;
            const float* Wz = (gg == 0) ? p.Wzi : (gg == 1) ? p.Wzf : (gg == 2) ? p.Wzc : p.Wzo;
            ((float*)(smem + BZ_OFF))[tid] = b[nn];
            ((float*)(smem + ZW_OFF))[tid] = p.mz[gg] * Wz[nn];
        }
        if (tid >= 32 && tid < 72)  ((float*)(smem + WD1_OFF))[tid - 32] = p.Wd1[tid - 32];
        if (tid >= 72 && tid < 97)  ((float*)(smem + WD2_OFF))[tid - 72] = p.Wd2[tid - 72];
        if (tid >= 97 && tid < 102) {
            int q = tid - 97;
            ((float*)(smem + WD3_OFF))[q] = p.Wd3[q];
            ((float*)(smem + BD1_OFF))[q] = p.bd1[q];
            ((float*)(smem + BD2_OFF))[q] = p.bd2[q];
            ((float*)(smem + M1_OFF))[q]  = p.m1[q];
            ((float*)(smem + M2_OFF))[q]  = p.m2[q];
        }
        if (tid == 102) ((float*)(smem + BD3_OFF))[0] = p.bd3[0];
    }
    __syncthreads();

    // stage issue: 2 tensor ops (x) + 1 bulk (W), all from tid 0
    auto issue = [&](int s) {
        int buf = s & 1;
        uint32_t mbar = smem_u32 + MBAR_OFF + 8u * buf;
        mbar_expect_tx(mbar, STAGE_BYTES);
        uint32_t dstx = smem_u32 + XS_OFF + (uint32_t)buf * XS_SZ;
        tma2d(dstx,         tmp_x, s * KC,      cta_row0, mbar);
        tma2d(dstx + 16384, tmp_x, s * KC + 32, cta_row0, mbar);
        uint32_t dstw = smem_u32 + WS_OFF + (uint32_t)buf * WS_SZ;
        bulk_g2s(dstw, (const char*)g_Bp + (size_t)s * WS_SZ, WS_SZ, mbar);
    };
    if (tid == 0) { issue(0); issue(1); }

    float acc[4][4];
#pragma unroll
    for (int nt = 0; nt < 4; nt++)
#pragma unroll
        for (int q = 0; q < 4; q++) acc[nt][q] = 0.0f;

    int ph0 = 0, ph1 = 0;
    const uint32_t xorg = (uint32_t)g << 4;      // SW128 row-xor (row&7 == g for both rows)

    for (int s = 0; s < NSTAGES; s++) {
        int buf = s & 1;
        if (buf == 0) { mbar_wait(smem_u32 + MBAR_OFF + 0, ph0); ph0 ^= 1; }
        else          { mbar_wait(smem_u32 + MBAR_OFF + 8, ph1); ph1 ^= 1; }

        const char* xsb = smem + XS_OFF + buf * XS_SZ;
        const uint4* ws = (const uint4*)(smem + WS_OFF + buf * WS_SZ);
        const char* r0b = xsb + lr0 * 128;
        const char* r1b = xsb + lr1 * 128;

#pragma unroll
        for (int kt = 0; kt < 4; kt++) {
            const int stb = (kt >> 1) * 16384;
            const uint32_t c0 = ((uint32_t)(64 * (kt & 1) + 8 * t4)) ^ xorg;
            const uint32_t c1 = ((uint32_t)(64 * (kt & 1) + 8 * t4 + 32)) ^ xorg;
            float2 xa = *(const float2*)(r0b + stb + c0);
            float2 xb = *(const float2*)(r0b + stb + c1);
            float2 xc = *(const float2*)(r1b + stb + c0);
            float2 xd = *(const float2*)(r1b + stb + c1);
            uint32_t ah0 = cvtbf2(xa.y, xa.x);
            uint32_t ah1 = cvtbf2(xc.y, xc.x);
            uint32_t ah2 = cvtbf2(xb.y, xb.x);
            uint32_t ah3 = cvtbf2(xd.y, xd.x);
            uint32_t al0 = cvtbf2(xa.y - bf_hi(ah0), xa.x - bf_lo(ah0));
            uint32_t al1 = cvtbf2(xc.y - bf_hi(ah1), xc.x - bf_lo(ah1));
            uint32_t al2 = cvtbf2(xb.y - bf_hi(ah2), xb.x - bf_lo(ah2));
            uint32_t al3 = cvtbf2(xd.y - bf_hi(ah3), xd.x - bf_lo(ah3));
#pragma unroll
            for (int nt = 0; nt < 4; nt++) {
                uint4 bv = ws[(kt * 4 + nt) * 32 + lane];
                mma16816(acc[nt], ah0, ah1, ah2, ah3, bv.x, bv.y);   // xh @ Wh
                mma16816(acc[nt], al0, al1, al2, al3, bv.x, bv.y);   // xl @ Wh
                mma16816(acc[nt], ah0, ah1, ah2, ah3, bv.z, bv.w);   // xh @ Wl
            }
        }
        __syncthreads();
        if (tid == 0 && s + 2 < NSTAGES) issue(s + 2);
    }

    // exchange pre-activations: sg[row][n]
    float* sg = (float*)(smem + SG_OFF);
#pragma unroll
    for (int nt = 0; nt < 4; nt++) {
        *(float2*)&sg[lr0 * SGS + nt * 8 + 2 * t4] = make_float2(acc[nt][0], acc[nt][1]);
        *(float2*)&sg[lr1 * SGS + nt * 8 + 2 * t4] = make_float2(acc[nt][2], acc[nt][3]);
    }
    __syncthreads();

    if (tid < ROWS_PER_CTA) {
        const int rg = cta_row0 + tid;
        const float* sWh = (const float*)(smem + WH_OFF);
        const float* sbz = (const float*)(smem + BZ_OFF);
        const float* szw = (const float*)(smem + ZW_OFF);
        const float* sd1 = (const float*)(smem + WD1_OFF);
        const float* sb1 = (const float*)(smem + BD1_OFF);
        const float* sd2 = (const float*)(smem + WD2_OFF);
        const float* sb2 = (const float*)(smem + BD2_OFF);
        const float* sd3 = (const float*)(smem + WD3_OFF);
        const float  b3  = ((const float*)(smem + BD3_OFF))[0];
        const float* sm1 = (const float*)(smem + M1_OFF);
        const float* sm2 = (const float*)(smem + M2_OFF);

        float pre[32];
#pragma unroll
        for (int n = 0; n < 32; n++) pre[n] = sg[tid * SGS + n];

        float zv = p.zp[rg];
        float hv[8];
#pragma unroll
        for (int j = 0; j < 8; j++) hv[j] = p.hp[(size_t)rg * Hsz + j];

#pragma unroll
        for (int n = 0; n < 32; n++) pre[n] = fmaf(zv, szw[n], pre[n] + sbz[n]);
#pragma unroll
        for (int j = 0; j < 8; j++) {
#pragma unroll
            for (int n = 0; n < 32; n++) pre[n] = fmaf(hv[j], sWh[j * 32 + n], pre[n]);
        }

        float htv[8];
        float* out = p.out;
#pragma unroll
        for (int nn = 0; nn < 8; nn++) {
            float cprev = p.cp[(size_t)rg * Hsz + nn];
            float It = hsig(pre[nn]);
            float Ft = hsig(pre[8 + nn]);
            float Cc = tanhf(pre[16 + nn]);
            float Ot = hsig(pre[24 + nn]);
            float cn = fmaf(Ft, cprev, It * Cc);
            htv[nn] = Ot * tanhf(cn);
            out[(size_t)Bsz * 9 + (size_t)rg * Hsz + nn] = cn;       // ct
            out[(size_t)Bsz     + (size_t)rg * Hsz + nn] = htv[nn];  // ht
        }

        float t1[5];
#pragma unroll
        for (int q = 0; q < 5; q++) {
            float a = sb1[q];
#pragma unroll
            for (int nn = 0; nn < 8; nn++) a = fmaf(htv[nn], sd1[nn * 5 + q], a);
            t1[q] = fmaxf(a, 0.0f) * sm1[q];
        }
        float t2[5];
#pragma unroll
        for (int q = 0; q < 5; q++) {
            float a = sb2[q];
#pragma unroll
            for (int u = 0; u < 5; u++) a = fmaf(t1[u], sd2[u * 5 + q], a);
            t2[q] = fmaxf(a, 0.0f) * sm2[q];
        }
        float a3 = b3;
#pragma unroll
        for (int u = 0; u < 5; u++) a3 = fmaf(t2[u], sd3[u], a3);
        out[rg] = zv + fmaxf(a3, 0.0f);                              // zt
    }
}

typedef CUresult (*EncodeTiledFn)(
    CUtensorMap*, CUtensorMapDataType, cuuint32_t, void*,
    const cuuint64_t*, const cuuint64_t*, const cuuint32_t*, const cuuint32_t*,
    CUtensorMapInterleave, CUtensorMapSwizzle, CUtensorMapL2promotion, CUtensorMapFloatOOBfill);

extern "C" void kernel_launch(void* const* d_in, const int* in_sizes, int n_in,
                              void* d_out, int out_size) {
    KParams p;
    p.x   = (const float*)d_in[0];
    p.hp  = (const float*)d_in[1];
    p.cp  = (const float*)d_in[2];
    p.zp  = (const float*)d_in[3];
    const float* Wxi = (const float*)d_in[4];
    const float* Wxf = (const float*)d_in[5];
    const float* Wxc = (const float*)d_in[6];
    const float* Wxo = (const float*)d_in[7];
    p.Whi = (const float*)d_in[8];
    p.Whf = (const float*)d_in[9];
    p.Whc = (const float*)d_in[10];
    p.Who = (const float*)d_in[11];
    p.Wzi = (const float*)d_in[12];
    p.Wzf = (const float*)d_in[13];
    p.Wzc = (const float*)d_in[14];
    p.Wzo = (const float*)d_in[15];
    p.bi  = (const float*)d_in[16];
    p.bf  = (const float*)d_in[17];
    p.bc  = (const float*)d_in[18];
    p.bo  = (const float*)d_in[19];
    p.Wd1 = (const float*)d_in[20];
    p.bd1 = (const float*)d_in[21];
    p.Wd2 = (const float*)d_in[22];
    p.bd2 = (const float*)d_in[23];
    p.Wd3 = (const float*)d_in[24];
    p.bd3 = (const float*)d_in[25];
    const float* mx = (const float*)d_in[26];
    p.mz  = (const float*)d_in[27];
    p.m1  = (const float*)d_in[28];
    p.m2  = (const float*)d_in[29];
    p.out = (float*)d_out;

    // Build tensor map for x: [D=1024 inner, B=65536 outer], box [32, 128], SW128.
    EncodeTiledFn enc = nullptr;
    {
        void* fp = nullptr;
        cudaDriverEntryPointQueryResult qr;
        cudaGetDriverEntryPoint("cuTensorMapEncodeTiled", &fp, cudaEnableDefault, &qr);
        enc = (EncodeTiledFn)fp;
    }
    CUtensorMap tmx;
    {
        cuuint64_t dims[2]    = {(cuuint64_t)Dsz, (cuuint64_t)Bsz};
        cuuint64_t strides[1] = {(cuuint64_t)Dsz * sizeof(float)};
        cuuint32_t box[2]     = {32u, 128u};
        cuuint32_t estr[2]    = {1u, 1u};
        enc(&tmx, CU_TENSOR_MAP_DATA_TYPE_FLOAT32, 2, (void*)p.x,
            dims, strides, box, estr,
            CU_TENSOR_MAP_INTERLEAVE_NONE, CU_TENSOR_MAP_SWIZZLE_128B,
            CU_TENSOR_MAP_L2_PROMOTION_L2_128B, CU_TENSOR_MAP_FLOAT_OOB_FILL_NONE);
    }

    cudaFuncSetAttribute(lstm_kernel, cudaFuncAttributeMaxDynamicSharedMemorySize, SMEM_TOTAL);

    prep_B<<<(64 * 4 * 32 + 255) / 256, 256>>>(Wxi, Wxf, Wxc, Wxo, mx);
    lstm_kernel<<<Bsz / ROWS_PER_CTA, NT, SMEM_TOTAL>>>(p, tmx);
}

// round 16
// speedup vs baseline: 1.9169x; 1.0303x over previous
#include <cuda_runtime.h>
#include <cuda.h>
#include <cstdint>

#define Bsz   65536
#define Dsz   1024
#define Hsz   8

#define ROWS_PER_CTA 64
#define NT           128
#define KC           64
#define NSTAGES      16
#define SGS          34          // gate-exchange row stride (floats), EVEN -> float2-aligned

// smem layout (bytes)
#define MBAR_OFF   0             // 2 mbars
#define WH_OFF     64
#define BZ_OFF     1088
#define ZW_OFF     1216
#define WD1_OFF    1344
#define BD1_OFF    1504
#define WD2_OFF    1536
#define BD2_OFF    1664
#define WD3_OFF    1696
#define BD3_OFF    1720
#define M1_OFF     1728
#define M2_OFF     1760
#define XS_OFF     4096
#define XS_SZ      16384                              // 2 subtiles x (64 rows x 128B), SW128
#define WS_OFF     (XS_OFF + 2 * XS_SZ)               // 36864
#define WS_SZ      8192                               // 4 kt * 4 nt * 32 lanes * 16B
#define SMEM_TOTAL (WS_OFF + 2 * WS_SZ)               // 53248
#define SG_OFF     XS_OFF
#define STAGE_BYTES (XS_SZ + WS_SZ)                   // 24576

// pre-packed B fragments: [stage 16][kt 4][nt 4][lane 32] uint4 = (bh0,bh1,bl0,bl1)
__device__ __align__(16) uint4 g_Bp[NSTAGES * 4 * 4 * 32];

__device__ __forceinline__ uint32_t cvtbf2(float hi, float lo) {
    uint32_t r;
    asm("cvt.rn.bf16x2.f32 %0, %1, %2;" : "=r"(r) : "f"(hi), "f"(lo));
    return r;
}
__device__ __forceinline__ float bf_lo(uint32_t u) { return __uint_as_float(u << 16); }
__device__ __forceinline__ float bf_hi(uint32_t u) { return __uint_as_float(u & 0xffff0000u); }

__device__ __forceinline__ void mbar_init(uint32_t a, uint32_t cnt) {
    asm volatile("mbarrier.init.shared.b64 [%0], %1;" :: "r"(a), "r"(cnt) : "memory");
}
__device__ __forceinline__ void mbar_expect_tx(uint32_t a, uint32_t bytes) {
    asm volatile("mbarrier.arrive.expect_tx.shared.b64 _, [%0], %1;" :: "r"(a), "r"(bytes) : "memory");
}
__device__ __forceinline__ void mbar_wait(uint32_t a, uint32_t parity) {
    asm volatile(
        "{\n\t.reg .pred P;\n"
        "LW_%=:\n\t"
        "mbarrier.try_wait.parity.acquire.cta.shared::cta.b64 P, [%0], %1, 0x989680;\n\t"
        "@P bra LD_%=;\n\t"
        "bra LW_%=;\n"
        "LD_%=:\n\t}"
        :: "r"(a), "r"(parity) : "memory");
}
__device__ __forceinline__ void bulk_g2s(uint32_t dst, const void* src, uint32_t bytes, uint32_t mbar) {
    asm volatile(
        "cp.async.bulk.shared::cluster.global.mbarrier::complete_tx::bytes [%0], [%1], %2, [%3];"
        :: "r"(dst), "l"(src), "r"(bytes), "r"(mbar) : "memory");
}
__device__ __forceinline__ void tma2d(uint32_t dst, const CUtensorMap* tm, int c0, int c1, uint32_t mbar) {
    asm volatile(
        "cp.async.bulk.tensor.2d.shared::cluster.global.tile.mbarrier::complete_tx::bytes "
        "[%0], [%1, {%2, %3}], [%4];"
        :: "r"(dst), "l"(tm), "r"(c0), "r"(c1), "r"(mbar) : "memory");
}
__device__ __forceinline__ float hsig(float x) {
    return __saturatef(fmaf(x, 0.16666667f, 0.5f));
}
__device__ __forceinline__ void mma16816(float* c, uint32_t a0, uint32_t a1, uint32_t a2, uint32_t a3,
                                         uint32_t b0, uint32_t b1) {
    asm volatile(
        "mma.sync.aligned.m16n8k16.row.col.f32.bf16.bf16.f32 "
        "{%0,%1,%2,%3},{%4,%5,%6,%7},{%8,%9},{%0,%1,%2,%3};"
        : "+f"(c[0]), "+f"(c[1]), "+f"(c[2]), "+f"(c[3])
        : "r"(a0), "r"(a1), "r"(a2), "r"(a3), "r"(b0), "r"(b1));
}

// ---------------- prep: fold m_x into W, split bf16 hi/lo, pack mma B fragments ----------------
__global__ void prep_B(const float* __restrict__ Wxi, const float* __restrict__ Wxf,
                       const float* __restrict__ Wxc, const float* __restrict__ Wxo,
                       const float* __restrict__ mx) {
    int i = blockIdx.x * blockDim.x + threadIdx.x;
    if (i >= 64 * 4 * 32) return;
    int lane = i & 31;
    int nt   = (i >> 5) & 3;
    int ktg  = i >> 7;            // global k-tile 0..63
    int g    = lane >> 2;
    int t4   = lane & 3;
    int n    = nt * 8 + g;        // output col 0..31
    int gate = n >> 3, nn = n & 7;
    const float* W = (gate == 0) ? Wxi : (gate == 1) ? Wxf : (gate == 2) ? Wxc : Wxo;
    int kb = ktg * 16 + t4 * 2;
    float w00 = mx[gate * Dsz + kb]     * W[kb * Hsz + nn];
    float w01 = mx[gate * Dsz + kb + 1] * W[(kb + 1) * Hsz + nn];
    float w10 = mx[gate * Dsz + kb + 8] * W[(kb + 8) * Hsz + nn];
    float w11 = mx[gate * Dsz + kb + 9] * W[(kb + 9) * Hsz + nn];
    uint4 v;
    v.x = cvtbf2(w01, w00);
    v.y = cvtbf2(w11, w10);
    v.z = cvtbf2(w01 - bf_hi(v.x), w00 - bf_lo(v.x));
    v.w = cvtbf2(w11 - bf_hi(v.y), w10 - bf_lo(v.y));
    int stage = ktg >> 2, kt = ktg & 3;
    g_Bp[((stage * 4 + kt) * 4 + nt) * 32 + lane] = v;
}

struct KParams {
    const float *x, *hp, *cp, *zp;
    const float *Whi, *Whf, *Whc, *Who;
    const float *Wzi, *Wzf, *Wzc, *Wzo;
    const float *bi, *bf, *bc, *bo;
    const float *Wd1, *bd1, *Wd2, *bd2, *Wd3, *bd3;
    const float *mz, *m1, *m2;
    float *out;
};

__global__ void __launch_bounds__(NT, 4)
lstm_kernel(KParams p, const __grid_constant__ CUtensorMap tmx) {
    extern __shared__ char smem[];
    const int tid = threadIdx.x;
    const int w   = tid >> 5;        // warp = m-tile (16 rows), 0..3
    const int lane = tid & 31;
    const int g   = lane >> 2;
    const int t4  = lane & 3;
    const int lr0 = w * 16 + g;      // 0..63
    const int lr1 = lr0 + 8;
    const int cta_row0 = blockIdx.x * ROWS_PER_CTA;
    const CUtensorMap* tmp_x = &tmx;

    uint32_t smem_u32 = (uint32_t)__cvta_generic_to_shared(smem);

    if (tid == 0) {
        mbar_init(smem_u32 + MBAR_OFF + 0, 1);
        mbar_init(smem_u32 + MBAR_OFF + 8, 1);
    }
    {
        float* sWh = (float*)(smem + WH_OFF);
#pragma unroll
        for (int i = tid; i < 256; i += NT) {
            int j = i >> 5, n = i & 31, gg = n >> 3, nn = n & 7;
            const float* Wh = (gg == 0) ? p.Whi : (gg == 1) ? p.Whf : (gg == 2) ? p.Whc : p.Who;
            sWh[j * 32 + n] = Wh[j * Hsz + nn];
        }
        if (tid < 32) {
            int gg = tid >> 3, nn = tid & 7;
            const float* b  = (gg == 0) ? p.bi  : (gg == 1) ? p.bf  : (gg == 2) ? p.bc  : p.bo;
            const float* Wz = (gg == 0) ? p.Wzi : (gg == 1) ? p.Wzf : (gg == 2) ? p.Wzc : p.Wzo;
            ((float*)(smem + BZ_OFF))[tid] = b[nn];
            ((float*)(smem + ZW_OFF))[tid] = p.mz[gg] * Wz[nn];
        }
        if (tid >= 32 && tid < 72)  ((float*)(smem + WD1_OFF))[tid - 32] = p.Wd1[tid - 32];
        if (tid >= 72 && tid < 97)  ((float*)(smem + WD2_OFF))[tid - 72] = p.Wd2[tid - 72];
        if (tid >= 97 && tid < 102) {
            int q = tid - 97;
            ((float*)(smem + WD3_OFF))[q] = p.Wd3[q];
            ((float*)(smem + BD1_OFF))[q] = p.bd1[q];
            ((float*)(smem + BD2_OFF))[q] = p.bd2[q];
            ((float*)(smem + M1_OFF))[q]  = p.m1[q];
            ((float*)(smem + M2_OFF))[q]  = p.m2[q];
        }
        if (tid == 102) ((float*)(smem + BD3_OFF))[0] = p.bd3[0];
    }
    __syncthreads();

    // stage issue: 2 tensor ops (x) + 1 bulk (W), from tid 0
    auto issue = [&](int s) {
        int buf = s & 1;
        uint32_t mbar = smem_u32 + MBAR_OFF + 8u * buf;
        mbar_expect_tx(mbar, STAGE_BYTES);
        uint32_t dstx = smem_u32 + XS_OFF + (uint32_t)buf * XS_SZ;
        tma2d(dstx,        tmp_x, s * KC,      cta_row0, mbar);
        tma2d(dstx + 8192, tmp_x, s * KC + 32, cta_row0, mbar);
        uint32_t dstw = smem_u32 + WS_OFF + (uint32_t)buf * WS_SZ;
        bulk_g2s(dstw, (const char*)g_Bp + (size_t)s * WS_SZ, WS_SZ, mbar);
    };
    if (tid == 0) { issue(0); issue(1); }

    float acc[4][4];
#pragma unroll
    for (int nt = 0; nt < 4; nt++)
#pragma unroll
        for (int q = 0; q < 4; q++) acc[nt][q] = 0.0f;

    int ph0 = 0, ph1 = 0;
    const uint32_t xorg = (uint32_t)g << 4;      // SW128 row-xor (row&7 == g for both rows)

    for (int s = 0; s < NSTAGES; s++) {
        int buf = s & 1;
        if (buf == 0) { mbar_wait(smem_u32 + MBAR_OFF + 0, ph0); ph0 ^= 1; }
        else          { mbar_wait(smem_u32 + MBAR_OFF + 8, ph1); ph1 ^= 1; }

        const char* xsb = smem + XS_OFF + buf * XS_SZ;
        const uint4* ws = (const uint4*)(smem + WS_OFF + buf * WS_SZ);
        const char* r0b = xsb + lr0 * 128;
        const char* r1b = xsb + lr1 * 128;

#pragma unroll
        for (int kt = 0; kt < 4; kt++) {
            const int stb = (kt >> 1) * 8192;
            const uint32_t c0 = ((uint32_t)(64 * (kt & 1) + 8 * t4)) ^ xorg;
            const uint32_t c1 = ((uint32_t)(64 * (kt & 1) + 8 * t4 + 32)) ^ xorg;
            float2 xa = *(const float2*)(r0b + stb + c0);
            float2 xb = *(const float2*)(r0b + stb + c1);
            float2 xc = *(const float2*)(r1b + stb + c0);
            float2 xd = *(const float2*)(r1b + stb + c1);
            uint32_t ah0 = cvtbf2(xa.y, xa.x);
            uint32_t ah1 = cvtbf2(xc.y, xc.x);
            uint32_t ah2 = cvtbf2(xb.y, xb.x);
            uint32_t ah3 = cvtbf2(xd.y, xd.x);
            uint32_t al0 = cvtbf2(xa.y - bf_hi(ah0), xa.x - bf_lo(ah0));
            uint32_t al1 = cvtbf2(xc.y - bf_hi(ah1), xc.x - bf_lo(ah1));
            uint32_t al2 = cvtbf2(xb.y - bf_hi(ah2), xb.x - bf_lo(ah2));
            uint32_t al3 = cvtbf2(xd.y - bf_hi(ah3), xd.x - bf_lo(ah3));
#pragma unroll
            for (int nt = 0; nt < 4; nt++) {
                uint4 bv = ws[(kt * 4 + nt) * 32 + lane];
                mma16816(acc[nt], ah0, ah1, ah2, ah3, bv.x, bv.y);   // xh @ Wh
                mma16816(acc[nt], al0, al1, al2, al3, bv.x, bv.y);   // xl @ Wh
                mma16816(acc[nt], ah0, ah1, ah2, ah3, bv.z, bv.w);   // xh @ Wl
            }
        }
        __syncthreads();
        if (tid == 0 && s + 2 < NSTAGES) issue(s + 2);
    }

    // exchange pre-activations: sg[row][n]
    float* sg = (float*)(smem + SG_OFF);
#pragma unroll
    for (int nt = 0; nt < 4; nt++) {
        *(float2*)&sg[lr0 * SGS + nt * 8 + 2 * t4] = make_float2(acc[nt][0], acc[nt][1]);
        *(float2*)&sg[lr1 * SGS + nt * 8 + 2 * t4] = make_float2(acc[nt][2], acc[nt][3]);
    }
    __syncthreads();

    if (tid < ROWS_PER_CTA) {
        const int rg = cta_row0 + tid;
        const float* sWh = (const float*)(smem + WH_OFF);
        const float* sbz = (const float*)(smem + BZ_OFF);
        const float* szw = (const float*)(smem + ZW_OFF);
        const float* sd1 = (const float*)(smem + WD1_OFF);
        const float* sb1 = (const float*)(smem + BD1_OFF);
        const float* sd2 = (const float*)(smem + WD2_OFF);
        const float* sb2 = (const float*)(smem + BD2_OFF);
        const float* sd3 = (const float*)(smem + WD3_OFF);
        const float  b3  = ((const float*)(smem + BD3_OFF))[0];
        const float* sm1 = (const float*)(smem + M1_OFF);
        const float* sm2 = (const float*)(smem + M2_OFF);

        float pre[32];
#pragma unroll
        for (int n = 0; n < 32; n++) pre[n] = sg[tid * SGS + n];

        float zv = p.zp[rg];
        float hv[8];
#pragma unroll
        for (int j = 0; j < 8; j++) hv[j] = p.hp[(size_t)rg * Hsz + j];

#pragma unroll
        for (int n = 0; n < 32; n++) pre[n] = fmaf(zv, szw[n], pre[n] + sbz[n]);
#pragma unroll
        for (int j = 0; j < 8; j++) {
#pragma unroll
            for (int n = 0; n < 32; n++) pre[n] = fmaf(hv[j], sWh[j * 32 + n], pre[n]);
        }

        float htv[8];
        float* out = p.out;
#pragma unroll
        for (int nn = 0; nn < 8; nn++) {
            float cprev = p.cp[(size_t)rg * Hsz + nn];
            float It = hsig(pre[nn]);
            float Ft = hsig(pre[8 + nn]);
            float Cc = tanhf(pre[16 + nn]);
            float Ot = hsig(pre[24 + nn]);
            float cn = fmaf(Ft, cprev, It * Cc);
            htv[nn] = Ot * tanhf(cn);
            out[(size_t)Bsz * 9 + (size_t)rg * Hsz + nn] = cn;       // ct
            out[(size_t)Bsz     + (size_t)rg * Hsz + nn] = htv[nn];  // ht
        }

        float t1[5];
#pragma unroll
        for (int q = 0; q < 5; q++) {
            float a = sb1[q];
#pragma unroll
            for (int nn = 0; nn < 8; nn++) a = fmaf(htv[nn], sd1[nn * 5 + q], a);
            t1[q] = fmaxf(a, 0.0f) * sm1[q];
        }
        float t2[5];
#pragma unroll
        for (int q = 0; q < 5; q++) {
            float a = sb2[q];
#pragma unroll
            for (int u = 0; u < 5; u++) a = fmaf(t1[u], sd2[u * 5 + q], a);
            t2[q] = fmaxf(a, 0.0f) * sm2[q];
        }
        float a3 = b3;
#pragma unroll
        for (int u = 0; u < 5; u++) a3 = fmaf(t2[u], sd3[u], a3);
        out[rg] = zv + fmaxf(a3, 0.0f);                              // zt
    }
}

typedef CUresult (*EncodeTiledFn)(
    CUtensorMap*, CUtensorMapDataType, cuuint32_t, void*,
    const cuuint64_t*, const cuuint64_t*, const cuuint32_t*, const cuuint32_t*,
    CUtensorMapInterleave, CUtensorMapSwizzle, CUtensorMapL2promotion, CUtensorMapFloatOOBfill);

extern "C" void kernel_launch(void* const* d_in, const int* in_sizes, int n_in,
                              void* d_out, int out_size) {
    KParams p;
    p.x   = (const float*)d_in[0];
    p.hp  = (const float*)d_in[1];
    p.cp  = (const float*)d_in[2];
    p.zp  = (const float*)d_in[3];
    const float* Wxi = (const float*)d_in[4];
    const float* Wxf = (const float*)d_in[5];
    const float* Wxc = (const float*)d_in[6];
    const float* Wxo = (const float*)d_in[7];
    p.Whi = (const float*)d_in[8];
    p.Whf = (const float*)d_in[9];
    p.Whc = (const float*)d_in[10];
    p.Who = (const float*)d_in[11];
    p.Wzi = (const float*)d_in[12];
    p.Wzf = (const float*)d_in[13];
    p.Wzc = (const float*)d_in[14];
    p.Wzo = (const float*)d_in[15];
    p.bi  = (const float*)d_in[16];
    p.bf  = (const float*)d_in[17];
    p.bc  = (const float*)d_in[18];
    p.bo  = (const float*)d_in[19];
    p.Wd1 = (const float*)d_in[20];
    p.bd1 = (const float*)d_in[21];
    p.Wd2 = (const float*)d_in[22];
    p.bd2 = (const float*)d_in[23];
    p.Wd3 = (const float*)d_in[24];
    p.bd3 = (const float*)d_in[25];
    const float* mx = (const float*)d_in[26];
    p.mz  = (const float*)d_in[27];
    p.m1  = (const float*)d_in[28];
    p.m2  = (const float*)d_in[29];
    p.out = (float*)d_out;

    // Build tensor map for x: [D=1024 inner, B=65536 outer], box [32, 64], SW128.
    EncodeTiledFn enc = nullptr;
    {
        void* fp = nullptr;
        cudaDriverEntryPointQueryResult qr;
        cudaGetDriverEntryPoint("cuTensorMapEncodeTiled", &fp, cudaEnableDefault, &qr);
        enc = (EncodeTiledFn)fp;
    }
    CUtensorMap tmx;
    {
        cuuint64_t dims[2]    = {(cuuint64_t)Dsz, (cuuint64_t)Bsz};
        cuuint64_t strides[1] = {(cuuint64_t)Dsz * sizeof(float)};
        cuuint32_t box[2]     = {32u, 64u};
        cuuint32_t estr[2]    = {1u, 1u};
        enc(&tmx, CU_TENSOR_MAP_DATA_TYPE_FLOAT32, 2, (void*)p.x,
            dims, strides, box, estr,
            CU_TENSOR_MAP_INTERLEAVE_NONE, CU_TENSOR_MAP_SWIZZLE_128B,
            CU_TENSOR_MAP_L2_PROMOTION_L2_128B, CU_TENSOR_MAP_FLOAT_OOB_FILL_NONE);
    }

    cudaFuncSetAttribute(lstm_kernel, cudaFuncAttributeMaxDynamicSharedMemorySize, SMEM_TOTAL);

    prep_B<<<(64 * 4 * 32 + 255) / 256, 256>>>(Wxi, Wxf, Wxc, Wxo, mx);
    lstm_kernel<<<Bsz / ROWS_PER_CTA, NT, SMEM_TOTAL>>>(p, tmx);
}